// round 3
// baseline (speedup 1.0000x reference)
#include <cuda_runtime.h>
#include <cuda_fp16.h>
#include <cstdint>

// Problem constants (fixed dataset)
#define N_NODES 16384
#define EMB     500
#define IN_SZ   4096
#define MAX_E   524288
#define NMASK   (N_NODES - 1)

// ---------------- scratch (device globals; no allocation allowed) ----------
__device__ float g_h[N_NODES * EMB];     // sigmoid(x@wenc.T+benc)
__device__ float g_hgc[N_NODES * EMB];   // after graph conv
__device__ float g_dinv[N_NODES];
__device__ int   g_deg[N_NODES];
__device__ int   g_count[N_NODES];
__device__ int   g_off[N_NODES + 1];
__device__ int   g_cursor[N_NODES];
__device__ int   g_src[MAX_E];

// ---------------- small kernels --------------------------------------------
__global__ void zero_kernel() {
    int i = blockIdx.x * blockDim.x + threadIdx.x;
    if (i < 2 * N_NODES) {
        if (i < N_NODES) g_deg[i] = 0;
        else             g_count[i - N_NODES] = 0;
    }
}

// edge_index is int32 (JAX x64-disabled downcasts int64). Mask defensively so
// a wrong dtype shows up as rel_err, never as an address-space trap.
__global__ void count_kernel(const int* __restrict__ ei, int E) {
    int e = blockIdx.x * blockDim.x + threadIdx.x;
    if (e < E) {
        atomicAdd(&g_deg[ei[e] & NMASK], 1);        // row
        atomicAdd(&g_count[ei[E + e] & NMASK], 1);  // col
    }
}

__global__ void dinv_kernel() {
    int i = blockIdx.x * blockDim.x + threadIdx.x;
    if (i < N_NODES) {
        int d = g_deg[i];
        g_dinv[i] = (d > 0) ? rsqrtf((float)d) : 0.0f;
    }
}

// exclusive scan of g_count (16384 = 1024 threads x 16)
__global__ void scan_kernel() {
    __shared__ int sdata[1024];
    int t = threadIdx.x;
    int local[16];
    int sum = 0;
#pragma unroll
    for (int i = 0; i < 16; i++) {
        local[i] = sum;
        sum += g_count[t * 16 + i];
    }
    sdata[t] = sum;
    __syncthreads();
    for (int off = 1; off < 1024; off <<= 1) {
        int v = 0;
        if (t >= off) v = sdata[t - off];
        __syncthreads();
        if (t >= off) sdata[t] += v;
        __syncthreads();
    }
    int base = sdata[t] - sum;  // exclusive across threads
#pragma unroll
    for (int i = 0; i < 16; i++) {
        int o = base + local[i];
        g_off[t * 16 + i] = o;
        g_cursor[t * 16 + i] = o;
    }
    if (t == 1023) g_off[N_NODES] = base + sum;
}

__global__ void fill_kernel(const int* __restrict__ ei, int E) {
    int e = blockIdx.x * blockDim.x + threadIdx.x;
    if (e < E) {
        int col = ei[E + e] & NMASK;
        int slot = atomicAdd(&g_cursor[col], 1);
        g_src[slot < MAX_E ? slot : MAX_E - 1] = ei[e] & NMASK;
    }
}

// gather-based GCN aggregation: one block per destination node
__global__ __launch_bounds__(128)
void aggregate_kernel(const float* __restrict__ conv_weight) {
    int n = blockIdx.x;
    int t = threadIdx.x;
    float cw = conv_weight[0];
    float dn = g_dinv[n];
    int beg = g_off[n], end = g_off[n + 1];
    float acc0 = 0.f, acc1 = 0.f, acc2 = 0.f, acc3 = 0.f;
    for (int e = beg; e < end; e++) {
        int s = g_src[e];
        float coef = dn * g_dinv[s] * cw;
        const float* hs = g_h + (size_t)s * EMB;
        acc0 += coef * hs[t];
        acc1 += coef * hs[t + 128];
        acc2 += coef * hs[t + 256];
        if (t + 384 < EMB) acc3 += coef * hs[t + 384];
    }
    const float* hn = g_h + (size_t)n * EMB;
    float* on = g_hgc + (size_t)n * EMB;
    on[t] = acc0 + hn[t];
    on[t + 128] = acc1 + hn[t + 128];
    on[t + 256] = acc2 + hn[t + 256];
    if (t + 384 < EMB) on[t + 384] = acc3 + hn[t + 384];
}

// ---------------- fp16 tensor-core GEMM ------------------------------------
// C[M,N] = act(A[M,K] @ B[N,K]^T + bias), fp32 in/out, fp16 mma, fp32 accum.
// SIG: sigmoid activation. VEC: K%32==0 & vectorizable. NG: guard n<N.
// A_FROM_G: read A from g_hgc (ignore Aparam). C_TO_G: write C to g_h.
__device__ __forceinline__ void mma16816(float* c, const uint32_t* a, const uint32_t* b) {
    asm volatile(
        "mma.sync.aligned.m16n8k16.row.col.f32.f16.f16.f32 "
        "{%0,%1,%2,%3}, {%4,%5,%6,%7}, {%8,%9}, {%0,%1,%2,%3};\n"
        : "+f"(c[0]), "+f"(c[1]), "+f"(c[2]), "+f"(c[3])
        : "r"(a[0]), "r"(a[1]), "r"(a[2]), "r"(a[3]), "r"(b[0]), "r"(b[1]));
}

template <bool SIG, bool VEC, bool NG, bool A_FROM_G, bool C_TO_G>
__global__ __launch_bounds__(256)
void gemm_kernel(const float* __restrict__ Aparam, const float* __restrict__ B,
                 const float* __restrict__ bias, float* __restrict__ Cparam,
                 int M, int N, int K) {
    const float* A = A_FROM_G ? (const float*)g_hgc : Aparam;
    float*       C = C_TO_G   ? (float*)g_h         : Cparam;

    const int BK = 32;
    __shared__ __align__(16) __half As[128][40];  // 128x32 + pad 8
    __shared__ __align__(16) __half Bs[128][40];

    int tid = threadIdx.x;
    int m0 = blockIdx.y * 128;
    int n0 = blockIdx.x * 128;
    int lane = tid & 31, wid = tid >> 5;
    int wm = wid & 1, wn = wid >> 1;  // 2x4 warp grid; warp tile 64(m) x 32(n)
    int g = lane >> 2, c = lane & 3;

    float acc[4][4][4];
#pragma unroll
    for (int mt = 0; mt < 4; mt++)
#pragma unroll
        for (int nt = 0; nt < 4; nt++)
#pragma unroll
            for (int i = 0; i < 4; i++) acc[mt][nt][i] = 0.f;

    for (int k0 = 0; k0 < K; k0 += BK) {
        if (VEC) {
#pragma unroll
            for (int i = 0; i < 4; i++) {
                int q = tid + i * 256;       // 1024 float4 for A tile
                int row = q >> 3, kc = (q & 7) * 4;
                float4 v = *(const float4*)(A + (size_t)(m0 + row) * K + k0 + kc);
                *(__half2*)&As[row][kc]     = __floats2half2_rn(v.x, v.y);
                *(__half2*)&As[row][kc + 2] = __floats2half2_rn(v.z, v.w);
            }
#pragma unroll
            for (int i = 0; i < 4; i++) {
                int q = tid + i * 256;
                int row = q >> 3, kc = (q & 7) * 4;
                int n = n0 + row;
                float4 v = make_float4(0.f, 0.f, 0.f, 0.f);
                if (!NG || n < N) v = *(const float4*)(B + (size_t)n * K + k0 + kc);
                *(__half2*)&Bs[row][kc]     = __floats2half2_rn(v.x, v.y);
                *(__half2*)&Bs[row][kc + 2] = __floats2half2_rn(v.z, v.w);
            }
        } else {
#pragma unroll
            for (int i = 0; i < 16; i++) {
                int q = tid + i * 256;       // 4096 scalars
                int row = q >> 5, kc = q & 31;
                int k = k0 + kc;
                float va = (k < K) ? A[(size_t)(m0 + row) * K + k] : 0.f;
                As[row][kc] = __float2half_rn(va);
                int n = n0 + row;
                float vb = (k < K && (!NG || n < N)) ? B[(size_t)n * K + k] : 0.f;
                Bs[row][kc] = __float2half_rn(vb);
            }
        }
        __syncthreads();

#pragma unroll
        for (int ks = 0; ks < 32; ks += 16) {
            uint32_t af[4][4], bf[4][2];
#pragma unroll
            for (int mt = 0; mt < 4; mt++) {
                int r = wm * 64 + mt * 16 + g;
                af[mt][0] = *(const uint32_t*)&As[r][ks + c * 2];
                af[mt][1] = *(const uint32_t*)&As[r + 8][ks + c * 2];
                af[mt][2] = *(const uint32_t*)&As[r][ks + c * 2 + 8];
                af[mt][3] = *(const uint32_t*)&As[r + 8][ks + c * 2 + 8];
            }
#pragma unroll
            for (int nt = 0; nt < 4; nt++) {
                int rn = wn * 32 + nt * 8 + g;
                bf[nt][0] = *(const uint32_t*)&Bs[rn][ks + c * 2];
                bf[nt][1] = *(const uint32_t*)&Bs[rn][ks + c * 2 + 8];
            }
#pragma unroll
            for (int mt = 0; mt < 4; mt++)
#pragma unroll
                for (int nt = 0; nt < 4; nt++)
                    mma16816(acc[mt][nt], af[mt], bf[nt]);
        }
        __syncthreads();
    }

    // epilogue
#pragma unroll
    for (int mt = 0; mt < 4; mt++) {
#pragma unroll
        for (int nt = 0; nt < 4; nt++) {
#pragma unroll
            for (int i = 0; i < 4; i++) {
                int m = m0 + wm * 64 + mt * 16 + g + ((i & 2) ? 8 : 0);
                int n = n0 + wn * 32 + nt * 8 + c * 2 + (i & 1);
                if (!NG || n < N) {
                    float v = acc[mt][nt][i] + bias[n];
                    if (SIG) v = 1.0f / (1.0f + __expf(-v));
                    C[(size_t)m * N + n] = v;
                }
            }
        }
    }
}

// ---------------- launch ----------------------------------------------------
extern "C" void kernel_launch(void* const* d_in, const int* in_sizes, int n_in,
                              void* d_out, int out_size) {
    const float* x    = (const float*)d_in[0];
    const int*   ei   = (const int*)d_in[1];     // int32 (JAX x64 disabled)
    const float* wenc = (const float*)d_in[2];
    const float* benc = (const float*)d_in[3];
    const float* wdec = (const float*)d_in[4];
    const float* bdec = (const float*)d_in[5];
    const float* cw   = (const float*)d_in[6];
    float*       out  = (float*)d_out;

    int E = in_sizes[1] / 2;

    // CSR build pipeline
    zero_kernel<<<(2 * N_NODES + 511) / 512, 512>>>();
    count_kernel<<<(E + 255) / 256, 256>>>(ei, E);
    dinv_kernel<<<(N_NODES + 511) / 512, 512>>>();
    scan_kernel<<<1, 1024>>>();
    fill_kernel<<<(E + 255) / 256, 256>>>(ei, E);

    // encode: h = sigmoid(x @ wenc^T + benc)   [16384 x 500], K=4096
    {
        dim3 grid((EMB + 127) / 128, N_NODES / 128);
        gemm_kernel<true, true, true, false, true><<<grid, 256>>>(
            x, wenc, benc, nullptr, N_NODES, EMB, IN_SZ);
    }

    // graph conv (gather, deterministic accumulation per node)
    aggregate_kernel<<<N_NODES, 128>>>(cw);

    // decode: p = hgc @ wdec^T + bdec          [16384 x 4096], K=500
    {
        dim3 grid(IN_SZ / 128, N_NODES / 128);
        gemm_kernel<false, false, false, true, false><<<grid, 256>>>(
            nullptr, wdec, bdec, out, N_NODES, IN_SZ, EMB);
    }
}

// round 4
// speedup vs baseline: 1.6917x; 1.6917x over previous
#include <cuda_runtime.h>
#include <cuda_fp16.h>
#include <cstdint>

// Problem constants (fixed dataset)
#define N_NODES 16384
#define EMB     500
#define EMBP    512          // padded embedding dim (zeros beyond 500)
#define IN_SZ   4096
#define MAX_E   524288
#define NMASK   (N_NODES - 1)

// ---------------- scratch (device globals; no allocation allowed) ----------
__device__ __align__(16) __half g_xh[(size_t)N_NODES * IN_SZ];   // x in fp16
__device__ __align__(16) __half g_wench[EMBP * IN_SZ];           // wenc fp16, rows 500..511 = 0
__device__ __align__(16) float  g_bencp[EMBP];                   // benc padded with 0
__device__ __align__(16) __half g_wdech[IN_SZ * EMBP];           // wdec fp16, cols 500..511 = 0
__device__ __align__(16) __half g_hh[N_NODES * EMBP];            // sigmoid output, fp16
__device__ __align__(16) __half g_hgch[N_NODES * EMBP];          // post graph-conv, fp16
__device__ float g_dinv[N_NODES];
__device__ int   g_deg[N_NODES];
__device__ int   g_count[N_NODES];
__device__ int   g_off[N_NODES + 1];
__device__ int   g_cursor[N_NODES];
__device__ int   g_src[MAX_E];

// ---------------- conversion prologue kernels -------------------------------
__global__ void conv_x_kernel(const float4* __restrict__ x) {
    size_t i = (size_t)blockIdx.x * blockDim.x + threadIdx.x;  // one float4 each
    float4 v = x[i];
    __half2* d = (__half2*)g_xh;
    d[i * 2]     = __floats2half2_rn(v.x, v.y);
    d[i * 2 + 1] = __floats2half2_rn(v.z, v.w);
}

__global__ void conv_wenc_kernel(const float* __restrict__ wenc) {
    int q = blockIdx.x * blockDim.x + threadIdx.x;   // quad of dest halfs
    int row = q >> 10;                 // 4096/4 = 1024 quads per row
    int c4 = (q & 1023) * 4;
    __half2 h0, h1;
    if (row < EMB) {
        float4 v = *(const float4*)(wenc + (size_t)row * IN_SZ + c4);
        h0 = __floats2half2_rn(v.x, v.y);
        h1 = __floats2half2_rn(v.z, v.w);
    } else {
        h0 = __floats2half2_rn(0.f, 0.f);
        h1 = h0;
    }
    __half2* d = (__half2*)(g_wench + (size_t)row * IN_SZ + c4);
    d[0] = h0; d[1] = h1;
}

__global__ void conv_benc_kernel(const float* __restrict__ benc) {
    int i = blockIdx.x * blockDim.x + threadIdx.x;
    if (i < EMBP) g_bencp[i] = (i < EMB) ? benc[i] : 0.f;
}

__global__ void conv_wdec_kernel(const float* __restrict__ wdec) {
    int q = blockIdx.x * blockDim.x + threadIdx.x;   // quad of dest halfs
    int row = q >> 7;                  // 512/4 = 128 quads per row
    int c = (q & 127) * 4;
    __half2 h0, h1;
    if (c < EMB) {   // c is a multiple of 4; 496 < 500 so quad 496..499 valid
        float4 v = *(const float4*)(wdec + (size_t)row * EMB + c);
        h0 = __floats2half2_rn(v.x, v.y);
        h1 = __floats2half2_rn(v.z, v.w);
    } else {
        h0 = __floats2half2_rn(0.f, 0.f);
        h1 = h0;
    }
    __half2* d = (__half2*)(g_wdech + (size_t)row * EMBP + c);
    d[0] = h0; d[1] = h1;
}

// ---------------- CSR build --------------------------------------------------
__global__ void zero_kernel() {
    int i = blockIdx.x * blockDim.x + threadIdx.x;
    if (i < 2 * N_NODES) {
        if (i < N_NODES) g_deg[i] = 0;
        else             g_count[i - N_NODES] = 0;
    }
}

__global__ void count_kernel(const int* __restrict__ ei, int E) {
    int e = blockIdx.x * blockDim.x + threadIdx.x;
    if (e < E) {
        atomicAdd(&g_deg[ei[e] & NMASK], 1);        // row
        atomicAdd(&g_count[ei[E + e] & NMASK], 1);  // col
    }
}

__global__ void dinv_kernel() {
    int i = blockIdx.x * blockDim.x + threadIdx.x;
    if (i < N_NODES) {
        int d = g_deg[i];
        g_dinv[i] = (d > 0) ? rsqrtf((float)d) : 0.0f;
    }
}

__global__ void scan_kernel() {
    __shared__ int sdata[1024];
    int t = threadIdx.x;
    int local[16];
    int sum = 0;
#pragma unroll
    for (int i = 0; i < 16; i++) {
        local[i] = sum;
        sum += g_count[t * 16 + i];
    }
    sdata[t] = sum;
    __syncthreads();
    for (int off = 1; off < 1024; off <<= 1) {
        int v = 0;
        if (t >= off) v = sdata[t - off];
        __syncthreads();
        if (t >= off) sdata[t] += v;
        __syncthreads();
    }
    int base = sdata[t] - sum;
#pragma unroll
    for (int i = 0; i < 16; i++) {
        int o = base + local[i];
        g_off[t * 16 + i] = o;
        g_cursor[t * 16 + i] = o;
    }
    if (t == 1023) g_off[N_NODES] = base + sum;
}

__global__ void fill_kernel(const int* __restrict__ ei, int E) {
    int e = blockIdx.x * blockDim.x + threadIdx.x;
    if (e < E) {
        int col = ei[E + e] & NMASK;
        int slot = atomicAdd(&g_cursor[col], 1);
        g_src[slot < MAX_E ? slot : MAX_E - 1] = ei[e] & NMASK;
    }
}

// ---------------- GCN aggregate (fp16 in/out, fp32 accumulate) --------------
__global__ __launch_bounds__(128)
void aggregate_kernel(const float* __restrict__ conv_weight) {
    int n = blockIdx.x;
    int t = threadIdx.x;
    float cw = conv_weight[0];
    float dn = g_dinv[n];
    int beg = g_off[n], end = g_off[n + 1];
    float a0 = 0.f, a1 = 0.f, a2 = 0.f, a3 = 0.f;
    for (int e = beg; e < end; e++) {
        int s = g_src[e];
        float coef = dn * g_dinv[s] * cw;
        uint2 r = *(const uint2*)(g_hh + (size_t)s * EMBP + t * 4);
        __half2 h0 = *(__half2*)&r.x, h1 = *(__half2*)&r.y;
        float2 p0 = __half22float2(h0), p1 = __half22float2(h1);
        a0 += coef * p0.x; a1 += coef * p0.y;
        a2 += coef * p1.x; a3 += coef * p1.y;
    }
    uint2 rs = *(const uint2*)(g_hh + (size_t)n * EMBP + t * 4);
    __half2 s0 = *(__half2*)&rs.x, s1 = *(__half2*)&rs.y;
    float2 q0 = __half22float2(s0), q1 = __half22float2(s1);
    __half2 o0 = __floats2half2_rn(a0 + q0.x, a1 + q0.y);
    __half2 o1 = __floats2half2_rn(a2 + q1.x, a3 + q1.y);
    uint2 w;
    w.x = *(uint32_t*)&o0; w.y = *(uint32_t*)&o1;
    *(uint2*)(g_hgch + (size_t)n * EMBP + t * 4) = w;
}

// ---------------- fp16 tensor-core GEMM with cp.async double buffering ------
__device__ __forceinline__ void mma16816(float* c, const uint32_t* a, const uint32_t* b) {
    asm volatile(
        "mma.sync.aligned.m16n8k16.row.col.f32.f16.f16.f32 "
        "{%0,%1,%2,%3}, {%4,%5,%6,%7}, {%8,%9}, {%0,%1,%2,%3};\n"
        : "+f"(c[0]), "+f"(c[1]), "+f"(c[2]), "+f"(c[3])
        : "r"(a[0]), "r"(a[1]), "r"(a[2]), "r"(a[3]), "r"(b[0]), "r"(b[1]));
}

__device__ __forceinline__ void cpasync16(uint32_t dst, const void* src) {
    asm volatile("cp.async.cg.shared.global [%0], [%1], 16;\n" :: "r"(dst), "l"(src));
}

// PHASE 0: encode  h = sigmoid(g_xh @ g_wench^T + g_bencp) -> g_hh   [16384 x 512], K=4096
// PHASE 1: decode  out = g_hgch @ g_wdech^T + bdec         [16384 x 4096], K=512
template <int PHASE>
__global__ __launch_bounds__(256, 2)
void gemm_async(const float* __restrict__ bias_in, float* __restrict__ Cout) {
    constexpr int K   = (PHASE == 0) ? IN_SZ : EMBP;
    constexpr int LDA = (PHASE == 0) ? IN_SZ : EMBP;
    constexpr int LDB = (PHASE == 0) ? IN_SZ : EMBP;
    constexpr int LDC = (PHASE == 0) ? EMBP  : IN_SZ;
    const __half* A = (PHASE == 0) ? g_xh    : g_hgch;
    const __half* B = (PHASE == 0) ? g_wench : g_wdech;
    const float* bias = (PHASE == 0) ? g_bencp : bias_in;

    __shared__ __align__(16) __half As[2][128][40];   // 80 B/row, 16B-aligned chunks
    __shared__ __align__(16) __half Bs[2][128][40];

    int tid = threadIdx.x;
    int m0 = blockIdx.y * 128;
    int n0 = blockIdx.x * 128;
    int lane = tid & 31, wid = tid >> 5;
    int wm = wid & 1, wn = wid >> 1;   // 2x4 warps; warp tile 64(m) x 32(n)
    int g = lane >> 2, c = lane & 3;

    uint32_t sA = (uint32_t)__cvta_generic_to_shared(&As[0][0][0]);
    uint32_t sB = (uint32_t)__cvta_generic_to_shared(&Bs[0][0][0]);

    // two 16B chunks of A and B per thread per stage
    int r0 = tid >> 2,        c0 = tid & 3;          // chunk tid
    int r1 = (tid + 256) >> 2, c1 = (tid + 256) & 3; // chunk tid+256

    float acc[4][4][4];
#pragma unroll
    for (int mt = 0; mt < 4; mt++)
#pragma unroll
        for (int nt = 0; nt < 4; nt++)
#pragma unroll
            for (int i = 0; i < 4; i++) acc[mt][nt][i] = 0.f;

    auto load_stage = [&](int st, int k0) {
        uint32_t ba = sA + st * (128 * 80);
        uint32_t bb = sB + st * (128 * 80);
        cpasync16(ba + r0 * 80 + c0 * 16, A + (size_t)(m0 + r0) * LDA + k0 + c0 * 8);
        cpasync16(ba + r1 * 80 + c1 * 16, A + (size_t)(m0 + r1) * LDA + k0 + c1 * 8);
        cpasync16(bb + r0 * 80 + c0 * 16, B + (size_t)(n0 + r0) * LDB + k0 + c0 * 8);
        cpasync16(bb + r1 * 80 + c1 * 16, B + (size_t)(n0 + r1) * LDB + k0 + c1 * 8);
    };

    constexpr int NK = K / 32;
    load_stage(0, 0);
    asm volatile("cp.async.commit_group;\n");

    for (int it = 0; it < NK; it++) {
        if (it + 1 < NK) {
            load_stage((it + 1) & 1, (it + 1) * 32);
            asm volatile("cp.async.commit_group;\n");
            asm volatile("cp.async.wait_group 1;\n");
        } else {
            asm volatile("cp.async.wait_group 0;\n");
        }
        __syncthreads();

        int st = it & 1;
#pragma unroll
        for (int ks = 0; ks < 32; ks += 16) {
            uint32_t af[4][4], bf[4][2];
#pragma unroll
            for (int mt = 0; mt < 4; mt++) {
                int r = wm * 64 + mt * 16 + g;
                af[mt][0] = *(const uint32_t*)&As[st][r][ks + c * 2];
                af[mt][1] = *(const uint32_t*)&As[st][r + 8][ks + c * 2];
                af[mt][2] = *(const uint32_t*)&As[st][r][ks + c * 2 + 8];
                af[mt][3] = *(const uint32_t*)&As[st][r + 8][ks + c * 2 + 8];
            }
#pragma unroll
            for (int nt = 0; nt < 4; nt++) {
                int rn = wn * 32 + nt * 8 + g;
                bf[nt][0] = *(const uint32_t*)&Bs[st][rn][ks + c * 2];
                bf[nt][1] = *(const uint32_t*)&Bs[st][rn][ks + c * 2 + 8];
            }
#pragma unroll
            for (int mt = 0; mt < 4; mt++)
#pragma unroll
                for (int nt = 0; nt < 4; nt++)
                    mma16816(acc[mt][nt], af[mt], bf[nt]);
        }
        __syncthreads();
    }

    // epilogue (pair stores; all dims padded, no guards)
#pragma unroll
    for (int mt = 0; mt < 4; mt++) {
#pragma unroll
        for (int nt = 0; nt < 4; nt++) {
            int n = n0 + wn * 32 + nt * 8 + c * 2;
            float b0 = bias[n], b1 = bias[n + 1];
#pragma unroll
            for (int half_row = 0; half_row < 2; half_row++) {
                int m = m0 + wm * 64 + mt * 16 + g + half_row * 8;
                float v0 = acc[mt][nt][half_row * 2 + 0] + b0;
                float v1 = acc[mt][nt][half_row * 2 + 1] + b1;
                if (PHASE == 0) {
                    v0 = 1.0f / (1.0f + __expf(-v0));
                    v1 = 1.0f / (1.0f + __expf(-v1));
                    __half2 h = __floats2half2_rn(v0, v1);
                    *(__half2*)(g_hh + (size_t)m * LDC + n) = h;
                } else {
                    float2 f = make_float2(v0, v1);
                    *(float2*)(Cout + (size_t)m * LDC + n) = f;
                }
            }
        }
    }
}

// ---------------- launch ----------------------------------------------------
extern "C" void kernel_launch(void* const* d_in, const int* in_sizes, int n_in,
                              void* d_out, int out_size) {
    const float* x    = (const float*)d_in[0];
    const int*   ei   = (const int*)d_in[1];     // int32 (JAX x64 disabled)
    const float* wenc = (const float*)d_in[2];
    const float* benc = (const float*)d_in[3];
    const float* wdec = (const float*)d_in[4];
    const float* bdec = (const float*)d_in[5];
    const float* cw   = (const float*)d_in[6];
    float*       out  = (float*)d_out;

    int E = in_sizes[1] / 2;

    // operand conversion prologue
    conv_x_kernel<<<(N_NODES * (IN_SZ / 4)) / 256, 256>>>((const float4*)x);
    conv_wenc_kernel<<<(EMBP * IN_SZ / 4) / 256, 256>>>(wenc);
    conv_benc_kernel<<<2, 256>>>(benc);
    conv_wdec_kernel<<<(IN_SZ * EMBP / 4) / 256, 256>>>(wdec);

    // CSR build pipeline
    zero_kernel<<<(2 * N_NODES + 511) / 512, 512>>>();
    count_kernel<<<(E + 255) / 256, 256>>>(ei, E);
    dinv_kernel<<<(N_NODES + 511) / 512, 512>>>();
    scan_kernel<<<1, 1024>>>();
    fill_kernel<<<(E + 255) / 256, 256>>>(ei, E);

    // encode: g_hh = sigmoid(x @ wenc^T + benc)   [16384 x 512], K=4096
    {
        dim3 grid(EMBP / 128, N_NODES / 128);
        gemm_async<0><<<grid, 256>>>(nullptr, nullptr);
    }

    // graph conv
    aggregate_kernel<<<N_NODES, 128>>>(cw);

    // decode: out = hgc @ wdec^T + bdec           [16384 x 4096], K=512
    {
        dim3 grid(IN_SZ / 128, N_NODES / 128);
        gemm_async<1><<<grid, 256>>>(bdec, out);
    }
}

// round 6
// speedup vs baseline: 1.8958x; 1.1206x over previous
#include <cuda_runtime.h>
#include <cuda_fp16.h>
#include <cstdint>

// Problem constants (fixed dataset)
#define N_NODES 16384
#define EMB     500
#define EMBP    512
#define IN_SZ   4096
#define MAX_E   524288
#define NMASK   (N_NODES - 1)

// ---------------- scratch (device globals) ----------------------------------
__device__ __align__(16) __half g_xh[(size_t)N_NODES * IN_SZ];
__device__ __align__(16) __half g_wench[EMBP * IN_SZ];
__device__ __align__(16) float  g_bencp[EMBP];
__device__ __align__(16) __half g_wdech[IN_SZ * EMBP];
__device__ __align__(16) __half g_hh[N_NODES * EMBP];
__device__ __align__(16) __half g_hgch[N_NODES * EMBP];
__device__ float g_dinv[N_NODES];
__device__ int   g_deg[N_NODES];
__device__ int   g_count[N_NODES];
__device__ int   g_off[N_NODES + 1];
__device__ int   g_cursor[N_NODES];
__device__ int   g_src[MAX_E];

// ---------------- conversion prologue ---------------------------------------
__global__ void conv_x_kernel(const float4* __restrict__ x) {
    size_t i = (size_t)blockIdx.x * blockDim.x + threadIdx.x;
    float4 v = x[i];
    __half2* d = (__half2*)g_xh;
    d[i * 2]     = __floats2half2_rn(v.x, v.y);
    d[i * 2 + 1] = __floats2half2_rn(v.z, v.w);
}

__global__ void conv_wenc_kernel(const float* __restrict__ wenc) {
    int q = blockIdx.x * blockDim.x + threadIdx.x;
    int row = q >> 10;
    int c4 = (q & 1023) * 4;
    __half2 h0, h1;
    if (row < EMB) {
        float4 v = *(const float4*)(wenc + (size_t)row * IN_SZ + c4);
        h0 = __floats2half2_rn(v.x, v.y);
        h1 = __floats2half2_rn(v.z, v.w);
    } else {
        h0 = __floats2half2_rn(0.f, 0.f);
        h1 = h0;
    }
    __half2* d = (__half2*)(g_wench + (size_t)row * IN_SZ + c4);
    d[0] = h0; d[1] = h1;
}

__global__ void conv_benc_kernel(const float* __restrict__ benc) {
    int i = blockIdx.x * blockDim.x + threadIdx.x;
    if (i < EMBP) g_bencp[i] = (i < EMB) ? benc[i] : 0.f;
}

__global__ void conv_wdec_kernel(const float* __restrict__ wdec) {
    int q = blockIdx.x * blockDim.x + threadIdx.x;
    int row = q >> 7;
    int c = (q & 127) * 4;
    __half2 h0, h1;
    if (c < EMB) {
        float4 v = *(const float4*)(wdec + (size_t)row * EMB + c);
        h0 = __floats2half2_rn(v.x, v.y);
        h1 = __floats2half2_rn(v.z, v.w);
    } else {
        h0 = __floats2half2_rn(0.f, 0.f);
        h1 = h0;
    }
    __half2* d = (__half2*)(g_wdech + (size_t)row * EMBP + c);
    d[0] = h0; d[1] = h1;
}

// ---------------- CSR build --------------------------------------------------
__global__ void zero_kernel() {
    int i = blockIdx.x * blockDim.x + threadIdx.x;
    if (i < 2 * N_NODES) {
        if (i < N_NODES) g_deg[i] = 0;
        else             g_count[i - N_NODES] = 0;
    }
}

__global__ void count_kernel(const int* __restrict__ ei, int E) {
    int e = blockIdx.x * blockDim.x + threadIdx.x;
    if (e < E) {
        atomicAdd(&g_deg[ei[e] & NMASK], 1);
        atomicAdd(&g_count[ei[E + e] & NMASK], 1);
    }
}

__global__ void dinv_kernel() {
    int i = blockIdx.x * blockDim.x + threadIdx.x;
    if (i < N_NODES) {
        int d = g_deg[i];
        g_dinv[i] = (d > 0) ? rsqrtf((float)d) : 0.0f;
    }
}

__global__ void scan_kernel() {
    __shared__ int sdata[1024];
    int t = threadIdx.x;
    int local[16];
    int sum = 0;
#pragma unroll
    for (int i = 0; i < 16; i++) {
        local[i] = sum;
        sum += g_count[t * 16 + i];
    }
    sdata[t] = sum;
    __syncthreads();
    for (int off = 1; off < 1024; off <<= 1) {
        int v = 0;
        if (t >= off) v = sdata[t - off];
        __syncthreads();
        if (t >= off) sdata[t] += v;
        __syncthreads();
    }
    int base = sdata[t] - sum;
#pragma unroll
    for (int i = 0; i < 16; i++) {
        int o = base + local[i];
        g_off[t * 16 + i] = o;
        g_cursor[t * 16 + i] = o;
    }
    if (t == 1023) g_off[N_NODES] = base + sum;
}

__global__ void fill_kernel(const int* __restrict__ ei, int E) {
    int e = blockIdx.x * blockDim.x + threadIdx.x;
    if (e < E) {
        int col = ei[E + e] & NMASK;
        int slot = atomicAdd(&g_cursor[col], 1);
        g_src[slot < MAX_E ? slot : MAX_E - 1] = ei[e] & NMASK;
    }
}

// ---------------- GCN aggregate ----------------------------------------------
__global__ __launch_bounds__(128)
void aggregate_kernel(const float* __restrict__ conv_weight) {
    int n = blockIdx.x;
    int t = threadIdx.x;
    float cw = conv_weight[0];
    float dn = g_dinv[n];
    int beg = g_off[n], end = g_off[n + 1];
    float a0 = 0.f, a1 = 0.f, a2 = 0.f, a3 = 0.f;
    for (int e = beg; e < end; e++) {
        int s = g_src[e];
        float coef = dn * g_dinv[s] * cw;
        uint2 r = *(const uint2*)(g_hh + (size_t)s * EMBP + t * 4);
        __half2 h0 = *(__half2*)&r.x, h1 = *(__half2*)&r.y;
        float2 p0 = __half22float2(h0), p1 = __half22float2(h1);
        a0 += coef * p0.x; a1 += coef * p0.y;
        a2 += coef * p1.x; a3 += coef * p1.y;
    }
    uint2 rs = *(const uint2*)(g_hh + (size_t)n * EMBP + t * 4);
    __half2 s0 = *(__half2*)&rs.x, s1 = *(__half2*)&rs.y;
    float2 q0 = __half22float2(s0), q1 = __half22float2(s1);
    __half2 o0 = __floats2half2_rn(a0 + q0.x, a1 + q0.y);
    __half2 o1 = __floats2half2_rn(a2 + q1.x, a3 + q1.y);
    uint2 w;
    w.x = *(uint32_t*)&o0; w.y = *(uint32_t*)&o1;
    *(uint2*)(g_hgch + (size_t)n * EMBP + t * 4) = w;
}

// ---------------- fp16 mma.sync GEMM: ldmatrix + 3-stage cp.async -----------
__device__ __forceinline__ void mma16816(float* c, const uint32_t* a, uint32_t b0, uint32_t b1) {
    asm volatile(
        "mma.sync.aligned.m16n8k16.row.col.f32.f16.f16.f32 "
        "{%0,%1,%2,%3}, {%4,%5,%6,%7}, {%8,%9}, {%0,%1,%2,%3};\n"
        : "+f"(c[0]), "+f"(c[1]), "+f"(c[2]), "+f"(c[3])
        : "r"(a[0]), "r"(a[1]), "r"(a[2]), "r"(a[3]), "r"(b0), "r"(b1));
}

__device__ __forceinline__ void ldsm4(uint32_t* r, uint32_t addr) {
    asm volatile("ldmatrix.sync.aligned.m8n8.x4.shared.b16 {%0,%1,%2,%3}, [%4];\n"
        : "=r"(r[0]), "=r"(r[1]), "=r"(r[2]), "=r"(r[3]) : "r"(addr));
}

__device__ __forceinline__ void cpasync16(uint32_t dst, const void* src) {
    asm volatile("cp.async.cg.shared.global [%0], [%1], 16;\n" :: "r"(dst), "l"(src));
}

#define STG      10240            // one operand tile (128 rows x 40 halfs x 2B)
#define SMEM_GEMM (6 * STG)       // 3 stages x (A + B)

// PHASE 0: encode  g_hh = sigmoid(g_xh @ g_wench^T + g_bencp)  [16384x512], K=4096
// PHASE 1: decode  out  = g_hgch @ g_wdech^T + bdec            [16384x4096], K=512
template <int PHASE>
__global__ __launch_bounds__(256, 2)
void gemm_async(const float* __restrict__ bias_in, float* __restrict__ Cout) {
    constexpr int K   = (PHASE == 0) ? IN_SZ : EMBP;
    constexpr int LDA = (PHASE == 0) ? IN_SZ : EMBP;
    constexpr int LDB = (PHASE == 0) ? IN_SZ : EMBP;
    constexpr int LDC = (PHASE == 0) ? EMBP  : IN_SZ;
    constexpr int NC  = K / 32;
    const __half* A = (PHASE == 0) ? g_xh    : g_hgch;
    const __half* B = (PHASE == 0) ? g_wench : g_wdech;
    const float* bias = (PHASE == 0) ? g_bencp : bias_in;

    extern __shared__ __align__(16) char smem[];
    uint32_t sA, sB;
    {
        uint32_t b;
        asm("{ .reg .u64 t; cvta.to.shared.u64 t, %1; cvt.u32.u64 %0, t; }" : "=r"(b) : "l"(smem));
        sA = b;
        sB = b + 3 * STG;
    }

    int tid = threadIdx.x;
    int m0 = blockIdx.y * 128;
    int n0 = blockIdx.x * 128;
    int lane = tid & 31, wid = tid >> 5;
    int wm = wid & 1, wn = wid >> 1;   // 2x4 warps; warp tile 64(m) x 32(n)

    // cp.async chunk coords (two 16B chunks of each operand per thread per stage)
    int r0 = tid >> 2,         c0 = tid & 3;
    int r1 = (tid + 256) >> 2, c1 = (tid + 256) & 3;

    // ldmatrix per-thread offsets
    int quad = lane >> 3, rin = lane & 7;
    // A x4: matrices {a0(m0-7,k0-7), a1(m8-15,k0-7), a2(m0-7,k8-15), a3(m8-15,k8-15)}
    uint32_t offA = (uint32_t)((wm * 64 + (quad & 1) * 8 + rin) * 80 + (quad >> 1) * 16);
    // B x4 over two n-tiles: {b0(n0-7), b1(n0-7), b0(n8-15), b1(n8-15)}
    uint32_t offB = (uint32_t)((wn * 32 + ((lane >> 4) & 1) * 8 + rin) * 80 + ((lane >> 3) & 1) * 16);

    float acc[4][4][4];
#pragma unroll
    for (int mt = 0; mt < 4; mt++)
#pragma unroll
        for (int nt = 0; nt < 4; nt++)
#pragma unroll
            for (int i = 0; i < 4; i++) acc[mt][nt][i] = 0.f;

    auto load_stage = [&](int st, int k0) {
        uint32_t ba = sA + st * STG;
        uint32_t bb = sB + st * STG;
        cpasync16(ba + r0 * 80 + c0 * 16, A + (size_t)(m0 + r0) * LDA + k0 + c0 * 8);
        cpasync16(ba + r1 * 80 + c1 * 16, A + (size_t)(m0 + r1) * LDA + k0 + c1 * 8);
        cpasync16(bb + r0 * 80 + c0 * 16, B + (size_t)(n0 + r0) * LDB + k0 + c0 * 8);
        cpasync16(bb + r1 * 80 + c1 * 16, B + (size_t)(n0 + r1) * LDB + k0 + c1 * 8);
    };

    load_stage(0, 0);
    asm volatile("cp.async.commit_group;\n");
    if (NC > 1) {
        load_stage(1, 32);
        asm volatile("cp.async.commit_group;\n");
    }

    for (int i = 0; i < NC; i++) {
        if (i + 2 < NC) {
            load_stage((i + 2) % 3, (i + 2) * 32);
            asm volatile("cp.async.commit_group;\n");
            asm volatile("cp.async.wait_group 2;\n");
        } else if (i + 1 < NC) {
            asm volatile("cp.async.wait_group 1;\n");
        } else {
            asm volatile("cp.async.wait_group 0;\n");
        }
        __syncthreads();

        int st = i % 3;
        uint32_t baseA = sA + st * STG + offA;
        uint32_t baseB = sB + st * STG + offB;
#pragma unroll
        for (int ks = 0; ks < 32; ks += 16) {
            uint32_t af[4][4], bf[2][4];
#pragma unroll
            for (int mt = 0; mt < 4; mt++)
                ldsm4(af[mt], baseA + mt * (16 * 80) + ks * 2);
#pragma unroll
            for (int ntp = 0; ntp < 2; ntp++)
                ldsm4(bf[ntp], baseB + ntp * (16 * 80) + ks * 2);
#pragma unroll
            for (int mt = 0; mt < 4; mt++) {
#pragma unroll
                for (int nt = 0; nt < 4; nt++)
                    mma16816(acc[mt][nt], af[mt], bf[nt >> 1][(nt & 1) * 2], bf[nt >> 1][(nt & 1) * 2 + 1]);
            }
        }
        __syncthreads();
    }

    // epilogue
    int g = lane >> 2, c = lane & 3;
#pragma unroll
    for (int mt = 0; mt < 4; mt++) {
#pragma unroll
        for (int nt = 0; nt < 4; nt++) {
            int n = n0 + wn * 32 + nt * 8 + c * 2;
            float b0 = bias[n], b1 = bias[n + 1];
#pragma unroll
            for (int hr = 0; hr < 2; hr++) {
                int m = m0 + wm * 64 + mt * 16 + g + hr * 8;
                float v0 = acc[mt][nt][hr * 2 + 0] + b0;
                float v1 = acc[mt][nt][hr * 2 + 1] + b1;
                if (PHASE == 0) {
                    v0 = 1.0f / (1.0f + __expf(-v0));
                    v1 = 1.0f / (1.0f + __expf(-v1));
                    *(__half2*)(g_hh + (size_t)m * LDC + n) = __floats2half2_rn(v0, v1);
                } else {
                    *(float2*)(Cout + (size_t)m * LDC + n) = make_float2(v0, v1);
                }
            }
        }
    }
}

// ---------------- launch ----------------------------------------------------
extern "C" void kernel_launch(void* const* d_in, const int* in_sizes, int n_in,
                              void* d_out, int out_size) {
    const float* x    = (const float*)d_in[0];
    const int*   ei   = (const int*)d_in[1];
    const float* wenc = (const float*)d_in[2];
    const float* benc = (const float*)d_in[3];
    const float* wdec = (const float*)d_in[4];
    const float* bdec = (const float*)d_in[5];
    const float* cw   = (const float*)d_in[6];
    float*       out  = (float*)d_out;

    int E = in_sizes[1] / 2;

    cudaFuncSetAttribute(gemm_async<0>, cudaFuncAttributeMaxDynamicSharedMemorySize, SMEM_GEMM);
    cudaFuncSetAttribute(gemm_async<1>, cudaFuncAttributeMaxDynamicSharedMemorySize, SMEM_GEMM);

    // operand conversion prologue
    conv_x_kernel<<<(N_NODES * (IN_SZ / 4)) / 256, 256>>>((const float4*)x);
    conv_wenc_kernel<<<(EMBP * IN_SZ / 4) / 256, 256>>>(wenc);
    conv_benc_kernel<<<2, 256>>>(benc);
    conv_wdec_kernel<<<(IN_SZ * EMBP / 4) / 256, 256>>>(wdec);

    // CSR build pipeline
    zero_kernel<<<(2 * N_NODES + 511) / 512, 512>>>();
    count_kernel<<<(E + 255) / 256, 256>>>(ei, E);
    dinv_kernel<<<(N_NODES + 511) / 512, 512>>>();
    scan_kernel<<<1, 1024>>>();
    fill_kernel<<<(E + 255) / 256, 256>>>(ei, E);

    // encode: [16384 x 512] = sigmoid(x @ wenc^T + benc), K=4096
    {
        dim3 grid(EMBP / 128, N_NODES / 128);
        gemm_async<0><<<grid, 256, SMEM_GEMM>>>(nullptr, nullptr);
    }

    // graph conv
    aggregate_kernel<<<N_NODES, 128>>>(cw);

    // decode: [16384 x 4096] = hgc @ wdec^T + bdec, K=512
    {
        dim3 grid(IN_SZ / 128, N_NODES / 128);
        gemm_async<1><<<grid, 256, SMEM_GEMM>>>(bdec, out);
    }
}